// round 11
// baseline (speedup 1.0000x reference)
#include <cuda_runtime.h>
#include <cuda_bf16.h>
#include <stdint.h>

// ---------------------------------------------------------------------------
// LennardJones: per-edge LJ energy + scatter-add of analytic forces to nodes.
// Outputs (flattened, concatenated):
//   d_out[0]              = potential_energy = 0.5 * (sum_n acc.w - E*e0)
//   d_out[1 .. 1+3N)      = forces          = -0.5 * analytic   (exact identity)
//   d_out[1+3N .. 1+6N)   = analytic_force  = segsum(f_scalar * bv)
//
// Structure: exactly TWO graph nodes (measured: each node costs ~2-4us of
// replay overhead regardless of size -> minimize node count).
//   1) lj_main_pad : one RED.v4 per edge {fs*x, fs*y, fs*z, pe_raw}
//      (measured R4->R5: L2 atomic cost ~ op count, not lanes; .w is free)
//   2) finalize_pad: writes both force arrays, re-zeros g_acc/g_misc to
//      restore the zero-state invariant for the next graph replay.
// ---------------------------------------------------------------------------

#define SCRATCH_CAP 131072  // >= n_nodes (100000)

__device__ float4 g_acc[SCRATCH_CAP];   // per-node {fx,fy,fz,pe_raw}, starts 0
struct Misc { double pe; unsigned ctr; unsigned pad; };
__device__ Misc g_misc;                 // finalize scratch, starts 0

// e0 = 4*((1/3)^12 - (1/3)^6) in double
#define E0_D (-5.479441744238777e-03)

// ---------------------------------------------------------------------------

__device__ __forceinline__ void edge_op_pad(float x, float y, float z, int n) {
    float r2  = fmaf(x, x, fmaf(y, y, z * z));
    float inv = __fdividef(1.0f, r2);
    float c6  = inv * inv * inv;
    float c12 = c6 * c6;
    float fs  = -24.0f * (2.0f * c12 - c6) * inv;
    float pe  = 4.0f * (c12 - c6);
    float4* p = &g_acc[n];
    asm volatile("red.global.add.v4.f32 [%0], {%1,%2,%3,%4};"
                 :: "l"(p), "f"(fs * x), "f"(fs * y), "f"(fs * z), "f"(pe)
                 : "memory");
}

__global__ void __launch_bounds__(256)
lj_main_pad(const float* __restrict__ bv, const int* __restrict__ dst, int E) {
    int t  = blockIdx.x * blockDim.x + threadIdx.x;
    int e0 = t * 4;
    if (e0 + 3 < E) {
        // 4 edges: 3x streaming LDG.128 coords + 1x streaming LDG.128 dst
        const float4* bv4  = reinterpret_cast<const float4*>(bv);
        const int4*   dst4 = reinterpret_cast<const int4*>(dst);
        float4 a = __ldcs(bv4 + 3 * t + 0);
        float4 b = __ldcs(bv4 + 3 * t + 1);
        float4 c = __ldcs(bv4 + 3 * t + 2);
        int4   d = __ldcs(dst4 + t);
        edge_op_pad(a.x, a.y, a.z, d.x);
        edge_op_pad(a.w, b.x, b.y, d.y);
        edge_op_pad(b.z, b.w, c.x, d.z);
        edge_op_pad(c.y, c.z, c.w, d.w);
    } else {
        for (int e = e0; e < E; e++)
            edge_op_pad(bv[3 * e], bv[3 * e + 1], bv[3 * e + 2], dst[e]);
    }
}

// ---------------------------------------------------------------------------
// Finalize: per-node thread. Writes both force arrays, re-zeros g_acc,
// reduces .w for PE; last block writes out[0] and resets g_misc.

__global__ void __launch_bounds__(256)
finalize_pad(float* __restrict__ out, int N, double pe_const) {
    int n = blockIdx.x * blockDim.x + threadIdx.x;
    float w = 0.0f;
    if (n < N) {
        float4 a = g_acc[n];
        g_acc[n] = make_float4(0.f, 0.f, 0.f, 0.f);  // restore invariant
        w = a.w;
        float* f  = out + 1 + 3 * n;
        float* af = out + 1 + 3 * N + 3 * n;
        f[0]  = -0.5f * a.x;  f[1]  = -0.5f * a.y;  f[2]  = -0.5f * a.z;
        af[0] = a.x;          af[1] = a.y;          af[2] = a.z;
    }

    // block reduction of w (8 warps)
    __shared__ float sred[8];
    unsigned lane = threadIdx.x & 31u;
    unsigned warp = threadIdx.x >> 5;
    #pragma unroll
    for (int off = 16; off > 0; off >>= 1)
        w += __shfl_down_sync(0xFFFFFFFFu, w, off);
    if (lane == 0) sred[warp] = w;
    __syncthreads();

    __shared__ bool is_last;
    if (threadIdx.x == 0) {
        float v = 0.0f;
        #pragma unroll
        for (int j = 0; j < 8; j++) v += sred[j];
        atomicAdd(&g_misc.pe, (double)v);
        __threadfence();
        is_last = (atomicAdd(&g_misc.ctr, 1u) == gridDim.x - 1);
    }
    __syncthreads();

    if (is_last && threadIdx.x == 0) {
        double total = atomicAdd(&g_misc.pe, 0.0);  // ordered read
        out[0] = (float)(0.5 * (total - pe_const));
        g_misc.pe  = 0.0;  // restore invariant for next replay
        g_misc.ctr = 0u;
    }
}

// ---------------------------------------------------------------------------
// Fallback path for N > SCRATCH_CAP (not expected at N=100000).

__global__ void lj_main_direct(const float* __restrict__ bv,
                               const int* __restrict__ dst,
                               float* __restrict__ acc, int E) {
    int e = blockIdx.x * blockDim.x + threadIdx.x;
    float pe = 0.0f;
    if (e < E) {
        float x = bv[3 * e], y = bv[3 * e + 1], z = bv[3 * e + 2];
        int n = dst[e];
        float r2  = fmaf(x, x, fmaf(y, y, z * z));
        float inv = __fdividef(1.0f, r2);
        float c6  = inv * inv * inv;
        float c12 = c6 * c6;
        float fs  = -24.0f * (2.0f * c12 - c6) * inv;
        atomicAdd(acc + 3 * n + 0, fs * x);
        atomicAdd(acc + 3 * n + 1, fs * y);
        atomicAdd(acc + 3 * n + 2, fs * z);
        pe = 4.0f * (c12 - c6);
    }
    #pragma unroll
    for (int off = 16; off > 0; off >>= 1)
        pe += __shfl_down_sync(0xFFFFFFFFu, pe, off);
    if ((threadIdx.x & 31u) == 0) atomicAdd(&g_misc.pe, (double)pe);
}

__global__ void finalize_direct(float* __restrict__ out, int N, double pe_const) {
    int i = blockIdx.x * blockDim.x + threadIdx.x;
    int total = 3 * N;
    if (i < total) out[1 + i] = -0.5f * out[1 + total + i];
    if (i == 0) {
        out[0] = (float)(0.5 * (g_misc.pe - pe_const));
        g_misc.pe = 0.0;
        g_misc.ctr = 0u;
    }
}

// ---------------------------------------------------------------------------

extern "C" void kernel_launch(void* const* d_in, const int* in_sizes, int n_in,
                              void* d_out, int out_size) {
    const float* bv  = (const float*)d_in[0];
    const int*   dst = (const int*)d_in[1];
    float* out = (float*)d_out;

    int E = in_sizes[1];
    int N = (out_size - 1) / 6;
    double pe_const = (double)E * E0_D;

    if (N <= SCRATCH_CAP) {
        // 1) main edge kernel (relies on zero-state invariant)
        {
            int threads = 256;
            int nt = (E + 3) / 4;
            int blocks = (nt + threads - 1) / threads;
            lj_main_pad<<<blocks, threads>>>(bv, dst, E);
        }
        // 2) finalize (writes outputs + restores zero-state)
        {
            int threads = 256;
            int blocks = (N + threads - 1) / threads;
            finalize_pad<<<blocks, threads>>>(out, N, pe_const);
        }
    } else {
        float* acc = out + 1 + 3 * N;
        cudaMemsetAsync(acc, 0, (size_t)(3 * N) * sizeof(float), 0);
        int threads = 256;
        int blocks = (E + threads - 1) / threads;
        lj_main_direct<<<blocks, threads>>>(bv, dst, acc, E);
        int b2 = (3 * N + threads - 1) / threads;
        finalize_direct<<<b2, threads>>>(out, N, pe_const);
    }
}

// round 12
// speedup vs baseline: 1.1028x; 1.1028x over previous
#include <cuda_runtime.h>
#include <cuda_bf16.h>
#include <stdint.h>

// ---------------------------------------------------------------------------
// LennardJones: per-edge LJ energy + scatter-add of analytic forces to nodes.
// Outputs (flattened, concatenated):
//   d_out[0]              = potential_energy = 0.5 * (sum_n acc.w - E*e0)
//   d_out[1 .. 1+3N)      = forces          = -0.5 * analytic   (exact identity)
//   d_out[1+3N .. 1+6N)   = analytic_force  = segsum(f_scalar * bv)
//
// Empirically-optimal composition (R2..R11 measurements):
//   - memset graph nodes for zeroing        (~0.2us, R10-R11 delta)
//   - PLAIN loads in main (NOT __ldcs: evict-first measured +7.5us)
//   - one RED.v4 per edge, PE rides free .w (R4->R5: cost ~ op count)
//   - finalize 128-thread blocks, no rezero (6.6us, R10)
// Main kernel (~37us) sits at the L2 RED-op throughput floor
// (~6.1us per M RED ops); loads are fully hidden under the atomics.
// ---------------------------------------------------------------------------

#define SCRATCH_CAP 131072  // >= n_nodes (100000)

__device__ float4 g_acc[SCRATCH_CAP];   // per-node {fx,fy,fz,pe_raw}
struct Misc { double pe; unsigned ctr; unsigned pad; };
__device__ Misc g_misc;                 // finalize scratch (one memset)

// e0 = 4*((1/3)^12 - (1/3)^6) in double
#define E0_D (-5.479441744238777e-03)

// ---------------------------------------------------------------------------

__device__ __forceinline__ void edge_op_pad(float x, float y, float z, int n) {
    float r2  = fmaf(x, x, fmaf(y, y, z * z));
    float inv = __fdividef(1.0f, r2);
    float c6  = inv * inv * inv;
    float c12 = c6 * c6;
    float fs  = -24.0f * (2.0f * c12 - c6) * inv;
    float pe  = 4.0f * (c12 - c6);
    float4* p = &g_acc[n];
    asm volatile("red.global.add.v4.f32 [%0], {%1,%2,%3,%4};"
                 :: "l"(p), "f"(fs * x), "f"(fs * y), "f"(fs * z), "f"(pe)
                 : "memory");
}

__global__ void __launch_bounds__(256)
lj_main_pad(const float* __restrict__ bv, const int* __restrict__ dst, int E) {
    int t  = blockIdx.x * blockDim.x + threadIdx.x;
    int e0 = t * 4;
    if (e0 + 3 < E) {
        // 4 edges: 3x LDG.128 coords (48B) + 1x LDG.128 dst (16B), plain policy
        const float4* bv4  = reinterpret_cast<const float4*>(bv);
        const int4*   dst4 = reinterpret_cast<const int4*>(dst);
        float4 a = bv4[3 * t + 0];
        float4 b = bv4[3 * t + 1];
        float4 c = bv4[3 * t + 2];
        int4   d = dst4[t];
        edge_op_pad(a.x, a.y, a.z, d.x);
        edge_op_pad(a.w, b.x, b.y, d.y);
        edge_op_pad(b.z, b.w, c.x, d.z);
        edge_op_pad(c.y, c.z, c.w, d.w);
    } else {
        for (int e = e0; e < E; e++)
            edge_op_pad(bv[3 * e], bv[3 * e + 1], bv[3 * e + 2], dst[e]);
    }
}

// ---------------------------------------------------------------------------
// Finalize: per-node thread (128/block). Writes both force arrays, reduces
// .w for PE; last block writes out[0]. No rezero (memset nodes handle it).

__global__ void __launch_bounds__(128)
finalize_pad(float* __restrict__ out, int N, double pe_const) {
    int n = blockIdx.x * blockDim.x + threadIdx.x;
    float w = 0.0f;
    if (n < N) {
        float4 a = g_acc[n];
        w = a.w;
        float* f  = out + 1 + 3 * n;
        float* af = out + 1 + 3 * N + 3 * n;
        f[0]  = -0.5f * a.x;  f[1]  = -0.5f * a.y;  f[2]  = -0.5f * a.z;
        af[0] = a.x;          af[1] = a.y;          af[2] = a.z;
    }

    // block reduction of w (4 warps)
    __shared__ float sred[4];
    unsigned lane = threadIdx.x & 31u;
    unsigned warp = threadIdx.x >> 5;
    #pragma unroll
    for (int off = 16; off > 0; off >>= 1)
        w += __shfl_down_sync(0xFFFFFFFFu, w, off);
    if (lane == 0) sred[warp] = w;
    __syncthreads();

    __shared__ bool is_last;
    if (threadIdx.x == 0) {
        float v = sred[0] + sred[1] + sred[2] + sred[3];
        atomicAdd(&g_misc.pe, (double)v);
        __threadfence();
        is_last = (atomicAdd(&g_misc.ctr, 1u) == gridDim.x - 1);
    }
    __syncthreads();

    if (is_last && threadIdx.x == 0) {
        double total = atomicAdd(&g_misc.pe, 0.0);  // ordered read
        out[0] = (float)(0.5 * (total - pe_const));
    }
}

// ---------------------------------------------------------------------------
// Fallback path for N > SCRATCH_CAP (not expected at N=100000).

__global__ void lj_main_direct(const float* __restrict__ bv,
                               const int* __restrict__ dst,
                               float* __restrict__ acc, int E) {
    int e = blockIdx.x * blockDim.x + threadIdx.x;
    float pe = 0.0f;
    if (e < E) {
        float x = bv[3 * e], y = bv[3 * e + 1], z = bv[3 * e + 2];
        int n = dst[e];
        float r2  = fmaf(x, x, fmaf(y, y, z * z));
        float inv = __fdividef(1.0f, r2);
        float c6  = inv * inv * inv;
        float c12 = c6 * c6;
        float fs  = -24.0f * (2.0f * c12 - c6) * inv;
        atomicAdd(acc + 3 * n + 0, fs * x);
        atomicAdd(acc + 3 * n + 1, fs * y);
        atomicAdd(acc + 3 * n + 2, fs * z);
        pe = 4.0f * (c12 - c6);
    }
    #pragma unroll
    for (int off = 16; off > 0; off >>= 1)
        pe += __shfl_down_sync(0xFFFFFFFFu, pe, off);
    if ((threadIdx.x & 31u) == 0) atomicAdd(&g_misc.pe, (double)pe);
}

__global__ void finalize_direct(float* __restrict__ out, int N, double pe_const) {
    int i = blockIdx.x * blockDim.x + threadIdx.x;
    int total = 3 * N;
    if (i < total) out[1 + i] = -0.5f * out[1 + total + i];
    if (i == 0) out[0] = (float)(0.5 * (g_misc.pe - pe_const));
}

// ---------------------------------------------------------------------------

extern "C" void kernel_launch(void* const* d_in, const int* in_sizes, int n_in,
                              void* d_out, int out_size) {
    const float* bv  = (const float*)d_in[0];
    const int*   dst = (const int*)d_in[1];
    float* out = (float*)d_out;

    int E = in_sizes[1];
    int N = (out_size - 1) / 6;
    double pe_const = (double)E * E0_D;

    void *p_acc = nullptr, *p_misc = nullptr;
    cudaGetSymbolAddress(&p_acc, g_acc);
    cudaGetSymbolAddress(&p_misc, g_misc);

    if (N <= SCRATCH_CAP) {
        // 1-2) zero accumulators + misc (memset graph nodes, ~free)
        cudaMemsetAsync(p_acc, 0, (size_t)N * sizeof(float4), 0);
        cudaMemsetAsync(p_misc, 0, sizeof(Misc), 0);

        // 3) main edge kernel: 4 edges/thread, one RED.v4 per edge
        {
            int threads = 256;
            int nt = (E + 3) / 4;
            int blocks = (nt + threads - 1) / threads;
            lj_main_pad<<<blocks, threads>>>(bv, dst, E);
        }
        // 4) finalize
        {
            int threads = 128;
            int blocks = (N + threads - 1) / threads;
            finalize_pad<<<blocks, threads>>>(out, N, pe_const);
        }
    } else {
        float* acc = out + 1 + 3 * N;
        cudaMemsetAsync(acc, 0, (size_t)(3 * N) * sizeof(float), 0);
        cudaMemsetAsync(p_misc, 0, sizeof(Misc), 0);
        int threads = 256;
        int blocks = (E + threads - 1) / threads;
        lj_main_direct<<<blocks, threads>>>(bv, dst, acc, E);
        int b2 = (3 * N + threads - 1) / threads;
        finalize_direct<<<b2, threads>>>(out, N, pe_const);
    }
}